// round 10
// baseline (speedup 1.0000x reference)
#include <cuda_runtime.h>
#include <cuda_fp16.h>
#include <cstdint>
#include <cstddef>

// ============================================================================
// RandomGraphMixer3D  ==  D[M=BT*N, 32] = gather(A)[M,512] @ W'[512,32] + bias
// R10 = R9 with double-r pipeline stages: stage = 2 r's, NBUF=2 x 5120B,
//       PF=1. Halves per-stage fixed overhead (shfl count, commit/wait pairs,
//       ring bookkeeping). Fragment layouts validated R5-R9.
// ============================================================================

#define BT_     16
#define NNODES_ 32768
#define NR_     16
#define NSTG_   8             // double-r stages per tile
#define NTILES_ 2048          // BT_ * NNODES_/256
#define GRID_   296           // 2 CTAs/SM

// SMEM layout (bytes)
#define OFF_B    0            // 32 KB B-frag table
#define OFF_BIAS 32768        // 128 B
#define OFF_A    32896        // 8 warps x 2 bufs x 5120 B
#define WARP_AB  10240
#define SMEM_TOTAL (32896 + 8*WARP_AB)   // 114816 -> 2 CTAs/SM

__device__ __forceinline__ uint32_t smem_u32(const void* p) {
    uint32_t a;
    asm("{ .reg .u64 t; cvta.to.shared.u64 t, %1; cvt.u32.u64 %0, t; }" : "=r"(a) : "l"(p));
    return a;
}
__device__ __forceinline__ void cp_async16(uint32_t dst, const void* src) {
    asm volatile("cp.async.cg.shared.global [%0], [%1], 16;" :: "r"(dst), "l"(src) : "memory");
}
__device__ __forceinline__ void cp_commit() {
    asm volatile("cp.async.commit_group;" ::: "memory");
}
template <int N> __device__ __forceinline__ void cp_wait() {
    asm volatile("cp.async.wait_group %0;" :: "n"(N) : "memory");
}
__device__ __forceinline__ void ldmatrix_x4(uint32_t& r0, uint32_t& r1,
                                            uint32_t& r2, uint32_t& r3, uint32_t a) {
    asm volatile("ldmatrix.sync.aligned.m8n8.x4.shared.b16 {%0,%1,%2,%3}, [%4];"
                 : "=r"(r0), "=r"(r1), "=r"(r2), "=r"(r3) : "r"(a));
}
__device__ __forceinline__ void lds128(uint32_t* v, uint32_t a) {
    asm volatile("ld.shared.v4.b32 {%0,%1,%2,%3}, [%4];"
                 : "=r"(v[0]), "=r"(v[1]), "=r"(v[2]), "=r"(v[3]) : "r"(a));
}
__device__ __forceinline__ void mma16816(float* c, const uint32_t* a,
                                         uint32_t b0, uint32_t b1) {
    asm volatile(
        "mma.sync.aligned.m16n8k16.row.col.f32.f16.f16.f32 "
        "{%0,%1,%2,%3}, {%4,%5,%6,%7}, {%8,%9}, {%0,%1,%2,%3};"
        : "+f"(c[0]), "+f"(c[1]), "+f"(c[2]), "+f"(c[3])
        : "r"(a[0]), "r"(a[1]), "r"(a[2]), "r"(a[3]), "r"(b0), "r"(b1));
}

// -------- scratch ------------------------------------------------------------
__device__ __align__(128) __half   g_xt[(size_t)BT_ * NNODES_ * 32];  // 32 MB
__device__ __align__(128) uint32_t g_Bfrag[8192];                      // 32 KB

// ============================================================================
// Kernel 1: x[b][c][n] f32 -> xt[b][n][c] f16 (validated R9)
// ============================================================================
__global__ void k_transpose(const float* __restrict__ x) {
    __shared__ float tile[32][132];
    int b  = blockIdx.x >> 8;
    int n0 = (blockIdx.x & 255) << 7;
    int tid = threadIdx.x;
    {
        int c = tid >> 3, f0 = tid & 7;
        const float4* xb = (const float4*)(x + ((size_t)b << 20)
                                             + ((size_t)c << 15) + n0);
        float4 v[4];
#pragma unroll
        for (int s = 0; s < 4; s++) v[s] = xb[f0 + 8 * s];
#pragma unroll
        for (int s = 0; s < 4; s++)
            *(float4*)&tile[c][4 * (f0 + 8 * s)] = v[s];
    }
    __syncthreads();
    {
        int node = tid & 127, h = tid >> 7;
        float f[16];
#pragma unroll
        for (int j = 0; j < 16; j++) f[j] = tile[16 * h + j][node];
        uint32_t u[8];
#pragma unroll
        for (int j = 0; j < 8; j++) {
            __half2 hh = __floats2half2_rn(f[2 * j], f[2 * j + 1]);
            u[j] = *(uint32_t*)&hh;
        }
        char* dst = (char*)g_xt + ((size_t)b << 21)
                  + (size_t)(n0 + node) * 64 + h * 32;
        *(uint4*)dst        = make_uint4(u[0], u[1], u[2], u[3]);
        *(uint4*)(dst + 16) = make_uint4(u[4], u[5], u[6], u[7]);
    }
}

// ============================================================================
// Kernel 1b: per-lane B fragment table (layout validated R5-R9).
// ============================================================================
__global__ void k_bfrag(const float* __restrict__ w) {
    for (int e = threadIdx.x; e < 8192; e += blockDim.x) {
        int lane = (e >> 2) & 31, j = e & 3;
        int chunk = (e >> 7) & 1, kc = (e >> 8) & 1, r = e >> 9;
        int nb = chunk * 2 + (j >> 1), reg = j & 1;
        int n_o = nb * 8 + (lane >> 2);
        int c = kc * 16 + 2 * (lane & 3) + reg * 8;
        __half lo = __float2half(w[n_o * 512 + c * 16 + r]);
        __half hi = __float2half(w[n_o * 512 + (c + 1) * 16 + r]);
        __half2 v = __halves2half2(lo, hi);
        g_Bfrag[e] = *(uint32_t*)&v;
    }
}

// ============================================================================
// Kernel 2: persistent gather-GEMM, double-r stages (296 CTAs x 256, 2/SM)
// ============================================================================
__global__ void __launch_bounds__(256, 2)
k_main(const float* __restrict__ bias, const int* __restrict__ idxg,
       float* __restrict__ out) {
    extern __shared__ char smem[];
    uint32_t sb = smem_u32(smem);
    int tid = threadIdx.x;
    int wid = tid >> 5, lane = tid & 31;

    int nt = 0;
    for (int t = blockIdx.x; t < NTILES_; t += GRID_) nt++;

    const float* bias_s = (const float*)(smem + OFF_BIAS);
    uint32_t aw_base = sb + OFF_A + (uint32_t)wid * WARP_AB;

    // idx registers: lane owns row `lane`; curi[q] packs r=2q (lo), 2q+1 (hi)
    uint32_t curi[8], nxti[8];
    auto idx_fetch = [&](int ti, uint32_t* dst) {
        int nbase = (ti & 127) << 8;
        const int4* src = (const int4*)idxg
                        + ((size_t)(nbase + wid * 32 + lane) << 2);
#pragma unroll
        for (int q = 0; q < 4; q++) {
            int4 v = __ldg(src + q);
            dst[2 * q]     = ((uint32_t)v.x & 0xFFFFu) | ((uint32_t)v.y << 16);
            dst[2 * q + 1] = ((uint32_t)v.z & 0xFFFFu) | ((uint32_t)v.w << 16);
        }
    };

    // gather stage rp (r = 2rp, 2rp+1) of tile-iter ip into buffer buf.
    // ONE shfl per row pair serves both r's (lo/hi u16).
    auto gather2 = [&](int ip, int rp, int buf, const uint32_t* idxp) {
        int t = blockIdx.x + ip * GRID_;
        int b = t >> 7;
        const char* xtb = (const char*)g_xt + ((size_t)b << 21);
        uint32_t abase = aw_base + (uint32_t)buf * 5120;
        int u = lane & 3;
        uint32_t pk = idxp[rp];
#pragma unroll
        for (int p = 0; p < 4; p++) {
            int row = (lane >> 2) + p * 8;
            uint32_t pr = __shfl_sync(0xffffffffu, pk, row);
            uint32_t g0 = pr & 0xFFFFu, g1 = pr >> 16;
            uint32_t dst = abase + (uint32_t)row * 80 + (uint32_t)u * 16;
            cp_async16(dst,        xtb + ((size_t)g0 << 6) + u * 16);
            cp_async16(dst + 2560, xtb + ((size_t)g1 << 6) + u * 16);
        }
    };

    // ---- prologue: B table + bias; idx(tile0); one stage prefetch ----
    {
        const char* src = (const char*)g_Bfrag;
#pragma unroll
        for (int k = 0; k < 8; k++)
            cp_async16(sb + OFF_B + (uint32_t)(tid + k * 256) * 16,
                       src + (tid + k * 256) * 16);
        if (tid < 8)
            cp_async16(sb + OFF_BIAS + (uint32_t)tid * 16,
                       (const char*)bias + tid * 16);
        cp_commit();
        cp_wait<0>();
        __syncthreads();     // only barrier (B-table visibility)
    }
    if (nt == 0) return;
    idx_fetch(blockIdx.x, curi);
    gather2(0, 0, 0, curi);
    cp_commit();

    uint32_t a_lane_off = (uint32_t)(lane & 15) * 80 + ((lane >> 4) << 4);
    uint32_t b_lane = sb + OFF_B + (uint32_t)lane * 16;

    int cons_buf = 0, pf_buf = 1;

    for (int i = 0; i < nt; i++) {
        int t = blockIdx.x + i * GRID_;
        int b = t >> 7;
        int nb_node = (t & 127) << 8;

        float C[2][4][4];
#pragma unroll
        for (int mb = 0; mb < 2; mb++)
#pragma unroll
            for (int nb = 0; nb < 4; nb++)
#pragma unroll
                for (int j = 0; j < 4; j++) C[mb][nb][j] = 0.0f;

#pragma unroll
        for (int sp = 0; sp < NSTG_; sp++) {
            if (sp == 0) {     // prefetch next tile's idx
                int tsafe = (i + 1 < nt) ? (blockIdx.x + (i + 1) * GRID_)
                                         : blockIdx.x;
                idx_fetch(tsafe, nxti);
            }
            if (sp == NSTG_ - 1) {   // PF=1: next gather is (i+1, 0)
#pragma unroll
                for (int q = 0; q < 8; q++) curi[q] = nxti[q];
            }
            {
                int ip = i + ((sp + 1) >> 3);
                int rp = (sp + 1) & 7;
                if (ip < nt) gather2(ip, rp, pf_buf, curi);
                cp_commit();               // 1 group per stage, always
                pf_buf ^= 1;
            }
            cp_wait<1>();

            uint32_t abase = aw_base + (uint32_t)cons_buf * 5120 + a_lane_off;
#pragma unroll
            for (int sub = 0; sub < 2; sub++) {
                int r = 2 * sp + sub;
                uint32_t abuf = abase + (uint32_t)sub * 2560;
                uint32_t bst = b_lane + (uint32_t)r * 2048;
#pragma unroll
                for (int kc = 0; kc < 2; kc++) {
                    uint32_t bf0[4], bf1[4];
                    lds128(bf0, bst + (uint32_t)kc * 1024);
                    lds128(bf1, bst + (uint32_t)kc * 1024 + 512);
#pragma unroll
                    for (int mb = 0; mb < 2; mb++) {
                        uint32_t a[4];
                        ldmatrix_x4(a[0], a[1], a[2], a[3],
                                    abuf + (uint32_t)mb * 1280 + kc * 32);
                        mma16816(C[mb][0], a, bf0[0], bf0[1]);
                        mma16816(C[mb][1], a, bf0[2], bf0[3]);
                        mma16816(C[mb][2], a, bf1[0], bf1[1]);
                        mma16816(C[mb][3], a, bf1[2], bf1[3]);
                    }
                }
            }
            cons_buf ^= 1;
        }

        // ---- epilogue: bias + store (layout validated R5-R9) ----
        {
            int oo = 2 * (lane & 3);
            float* ob0 = out + ((size_t)b << 20) + nb_node + wid * 32 + (lane >> 2);
#pragma unroll
            for (int mb = 0; mb < 2; mb++) {
                float* ob = ob0 + mb * 16;
#pragma unroll
                for (int nb = 0; nb < 4; nb++) {
                    int o = nb * 8 + oo;
                    float bo0 = bias_s[o], bo1 = bias_s[o + 1];
                    float* p = ob + ((size_t)o << 15);
                    p[0]             = C[mb][nb][0] + bo0;
                    p[1 << 15]       = C[mb][nb][1] + bo1;
                    p[8]             = C[mb][nb][2] + bo0;
                    p[(1 << 15) + 8] = C[mb][nb][3] + bo1;
                }
            }
        }
    }
}

// ============================================================================
extern "C" void kernel_launch(void* const* d_in, const int* in_sizes, int n_in,
                              void* d_out, int out_size) {
    const float* x    = (const float*)d_in[0];
    const float* w    = (const float*)d_in[1];
    const float* bias = (const float*)d_in[2];
    const int*   idx  = (const int*)d_in[3];
    float* out = (float*)d_out;

    (void)cudaFuncSetAttribute(k_main, cudaFuncAttributeMaxDynamicSharedMemorySize,
                               SMEM_TOTAL);

    k_transpose<<<BT_ * (NNODES_ / 128), 256>>>(x);
    k_bfrag<<<1, 256>>>(w);
    k_main<<<GRID_, 256, SMEM_TOTAL>>>(bias, idx, out);
}

// round 12
// speedup vs baseline: 1.0298x; 1.0298x over previous
#include <cuda_runtime.h>
#include <cuda_fp16.h>
#include <cstdint>
#include <cstddef>

// ============================================================================
// RandomGraphMixer3D  ==  D[M=BT*N, 32] = gather(A)[M,512] @ W'[512,32] + bias
// R12 = R11 resubmitted (previous round was an infra failure; source untested).
//      k_main = exact R9 (best measured; at L1 sector-wavefront floor).
//      Transpose = persistent double-buffered pipeline (592 blocks, next
//      tile's LDGs in flight across the single per-tile sync).
//      bfrag widened to 32 blocks.
// ============================================================================

#define BT_     16
#define NNODES_ 32768
#define NR_     16
#define NTILES_ 2048          // BT_ * NNODES_/256
#define NBUF_   4
#define PF_     3             // PF_ < NBUF_
#define GRID_   296           // 2 CTAs/SM
#define TGRID_  592           // transpose: 4 blocks/SM
#define TTILES_ 4096          // 128-node transpose tiles

// SMEM layout (bytes) -- k_main
#define OFF_B    0            // 32 KB B-frag table
#define OFF_BIAS 32768        // 128 B
#define OFF_A    32896        // 8 warps x 4 bufs x 2560 B
#define WARP_AB  10240
#define SMEM_TOTAL (32896 + 8*WARP_AB)   // 114816 -> 2 CTAs/SM

__device__ __forceinline__ uint32_t smem_u32(const void* p) {
    uint32_t a;
    asm("{ .reg .u64 t; cvta.to.shared.u64 t, %1; cvt.u32.u64 %0, t; }" : "=r"(a) : "l"(p));
    return a;
}
__device__ __forceinline__ void cp_async16(uint32_t dst, const void* src) {
    asm volatile("cp.async.cg.shared.global [%0], [%1], 16;" :: "r"(dst), "l"(src) : "memory");
}
__device__ __forceinline__ void cp_commit() {
    asm volatile("cp.async.commit_group;" ::: "memory");
}
template <int N> __device__ __forceinline__ void cp_wait() {
    asm volatile("cp.async.wait_group %0;" :: "n"(N) : "memory");
}
__device__ __forceinline__ void ldmatrix_x4(uint32_t& r0, uint32_t& r1,
                                            uint32_t& r2, uint32_t& r3, uint32_t a) {
    asm volatile("ldmatrix.sync.aligned.m8n8.x4.shared.b16 {%0,%1,%2,%3}, [%4];"
                 : "=r"(r0), "=r"(r1), "=r"(r2), "=r"(r3) : "r"(a));
}
__device__ __forceinline__ void lds128(uint32_t* v, uint32_t a) {
    asm volatile("ld.shared.v4.b32 {%0,%1,%2,%3}, [%4];"
                 : "=r"(v[0]), "=r"(v[1]), "=r"(v[2]), "=r"(v[3]) : "r"(a));
}
__device__ __forceinline__ void mma16816(float* c, const uint32_t* a,
                                         uint32_t b0, uint32_t b1) {
    asm volatile(
        "mma.sync.aligned.m16n8k16.row.col.f32.f16.f16.f32 "
        "{%0,%1,%2,%3}, {%4,%5,%6,%7}, {%8,%9}, {%0,%1,%2,%3};"
        : "+f"(c[0]), "+f"(c[1]), "+f"(c[2]), "+f"(c[3])
        : "r"(a[0]), "r"(a[1]), "r"(a[2]), "r"(a[3]), "r"(b0), "r"(b1));
}

// -------- scratch ------------------------------------------------------------
__device__ __align__(128) __half   g_xt[(size_t)BT_ * NNODES_ * 32];  // 32 MB
__device__ __align__(128) uint32_t g_Bfrag[8192];                      // 32 KB

// ============================================================================
// Kernel 1: x[b][c][n] f32 -> xt[b][n][c] f16.
// Persistent, double-buffered: LDG for tile i+1 issued before the single
// per-tile sync; smem read/convert/store of tile i overlaps that latency.
// ============================================================================
__global__ void __launch_bounds__(256)
k_transpose(const float* __restrict__ x) {
    __shared__ float tile[2][32][132];
    int tid = threadIdx.x;
    int c = tid >> 3, f0 = tid & 7;          // load mapping
    int node = tid & 127, h = tid >> 7;      // store mapping

    float4 v[4];
    // initial load (tile t0 = blockIdx.x)
    {
        int t = blockIdx.x;
        int b = t >> 8, n0 = (t & 255) << 7;
        const float4* xb = (const float4*)(x + ((size_t)b << 20)
                                             + ((size_t)c << 15) + n0);
#pragma unroll
        for (int s = 0; s < 4; s++) v[s] = xb[f0 + 8 * s];
    }

    int k = 0;
    for (int t = blockIdx.x; t < TTILES_; t += TGRID_, k++) {
        int buf = k & 1;
        // commit current tile's data to smem
#pragma unroll
        for (int s = 0; s < 4; s++)
            *(float4*)&tile[buf][c][4 * (f0 + 8 * s)] = v[s];
        // issue next tile's loads (in flight across sync + read phase)
        int nx = t + TGRID_;
        if (nx < TTILES_) {
            int b = nx >> 8, n0 = (nx & 255) << 7;
            const float4* xb = (const float4*)(x + ((size_t)b << 20)
                                                 + ((size_t)c << 15) + n0);
#pragma unroll
            for (int s = 0; s < 4; s++) v[s] = xb[f0 + 8 * s];
        }
        __syncthreads();
        // read + convert + store tile t
        {
            int b = t >> 8, n0 = (t & 255) << 7;
            float f[16];
#pragma unroll
            for (int j = 0; j < 16; j++) f[j] = tile[buf][16 * h + j][node];
            uint32_t u[8];
#pragma unroll
            for (int j = 0; j < 8; j++) {
                __half2 hh = __floats2half2_rn(f[2 * j], f[2 * j + 1]);
                u[j] = *(uint32_t*)&hh;
            }
            char* dst = (char*)g_xt + ((size_t)b << 21)
                      + (size_t)(n0 + node) * 64 + h * 32;
            *(uint4*)dst        = make_uint4(u[0], u[1], u[2], u[3]);
            *(uint4*)(dst + 16) = make_uint4(u[4], u[5], u[6], u[7]);
        }
        // buffer reuse (write at k+2) is fenced by the sync at k+1
    }
}

// ============================================================================
// Kernel 1b: per-lane B fragment table (layout validated R5-R10). 32 blocks.
// ============================================================================
__global__ void k_bfrag(const float* __restrict__ w) {
    int e = blockIdx.x * 256 + threadIdx.x;
    int lane = (e >> 2) & 31, j = e & 3;
    int chunk = (e >> 7) & 1, kc = (e >> 8) & 1, r = e >> 9;
    int nb = chunk * 2 + (j >> 1), reg = j & 1;
    int n_o = nb * 8 + (lane >> 2);
    int c = kc * 16 + 2 * (lane & 3) + reg * 8;
    __half lo = __float2half(w[n_o * 512 + c * 16 + r]);
    __half hi = __float2half(w[n_o * 512 + (c + 1) * 16 + r]);
    __half2 v = __halves2half2(lo, hi);
    g_Bfrag[e] = *(uint32_t*)&v;
}

// ============================================================================
// Kernel 2: persistent gather-GEMM (exact R9; 296 CTAs x 256, 2/SM)
// ============================================================================
__global__ void __launch_bounds__(256, 2)
k_main(const float* __restrict__ bias, const int* __restrict__ idxg,
       float* __restrict__ out) {
    extern __shared__ char smem[];
    uint32_t sb = smem_u32(smem);
    int tid = threadIdx.x;
    int wid = tid >> 5, lane = tid & 31;

    int nt = 0;
    for (int t = blockIdx.x; t < NTILES_; t += GRID_) nt++;

    const float* bias_s = (const float*)(smem + OFF_BIAS);
    uint32_t aw_base = sb + OFF_A + (uint32_t)wid * WARP_AB;

    uint32_t curi[8], nxti[8];
    auto idx_fetch = [&](int ti, uint32_t* dst) {
        int nbase = (ti & 127) << 8;
        const int4* src = (const int4*)idxg
                        + ((size_t)(nbase + wid * 32 + lane) << 2);
#pragma unroll
        for (int q = 0; q < 4; q++) {
            int4 v = __ldg(src + q);
            dst[2 * q]     = ((uint32_t)v.x & 0xFFFFu) | ((uint32_t)v.y << 16);
            dst[2 * q + 1] = ((uint32_t)v.z & 0xFFFFu) | ((uint32_t)v.w << 16);
        }
    };

    auto gather = [&](int ip, int r, int buf, const uint32_t* idxp) {
        int t = blockIdx.x + ip * GRID_;
        int b = t >> 7;
        const char* xtb = (const char*)g_xt + ((size_t)b << 21);
        uint32_t abase = aw_base + (uint32_t)buf * 2560;
        int u = lane & 3;
#pragma unroll
        for (int p = 0; p < 4; p++) {
            int row = (lane >> 2) + p * 8;
            uint32_t pk = __shfl_sync(0xffffffffu, idxp[r >> 1], row);
            uint32_t g = (r & 1) ? (pk >> 16) : (pk & 0xFFFFu);
            cp_async16(abase + (uint32_t)row * 80 + (uint32_t)u * 16,
                       xtb + ((size_t)g << 6) + u * 16);
        }
    };

    // ---- prologue: B table + bias; idx(tile0); PF gathers ----
    {
        const char* src = (const char*)g_Bfrag;
#pragma unroll
        for (int k = 0; k < 8; k++)
            cp_async16(sb + OFF_B + (uint32_t)(tid + k * 256) * 16,
                       src + (tid + k * 256) * 16);
        if (tid < 8)
            cp_async16(sb + OFF_BIAS + (uint32_t)tid * 16,
                       (const char*)bias + tid * 16);
        cp_commit();
        cp_wait<0>();
        __syncthreads();     // only barrier (B-table visibility)
    }
    if (nt == 0) return;
    idx_fetch(blockIdx.x, curi);
#pragma unroll
    for (int s = 0; s < PF_; s++) { gather(0, s, s, curi); cp_commit(); }

    uint32_t a_lane_off = (uint32_t)(lane & 15) * 80 + ((lane >> 4) << 4);
    uint32_t b_lane = sb + OFF_B + (uint32_t)lane * 16;

    int cons_buf = 0, pf_buf = PF_;

    for (int i = 0; i < nt; i++) {
        int t = blockIdx.x + i * GRID_;
        int b = t >> 7;
        int nb_node = (t & 127) << 8;

        float C[2][4][4];
#pragma unroll
        for (int mb = 0; mb < 2; mb++)
#pragma unroll
            for (int nb = 0; nb < 4; nb++)
#pragma unroll
                for (int j = 0; j < 4; j++) C[mb][nb][j] = 0.0f;

#pragma unroll
        for (int r = 0; r < NR_; r++) {
            if (r == 0) {
                int tsafe = (i + 1 < nt) ? (blockIdx.x + (i + 1) * GRID_)
                                         : blockIdx.x;
                idx_fetch(tsafe, nxti);
            }
            if (r == 13) {     // PF=3: gathers cross tile boundary at r>=13
#pragma unroll
                for (int q = 0; q < 8; q++) curi[q] = nxti[q];
            }
            {
                int ip  = i + ((r + PF_) >> 4);
                int pfr = (r + PF_) & 15;
                if (ip < nt) gather(ip, pfr, pf_buf, curi);
                cp_commit();
                if (++pf_buf == NBUF_) pf_buf = 0;
            }
            cp_wait<PF_>();

            uint32_t abuf = aw_base + (uint32_t)cons_buf * 2560 + a_lane_off;
            uint32_t bst = b_lane + (uint32_t)r * 2048;
#pragma unroll
            for (int kc = 0; kc < 2; kc++) {
                uint32_t bf0[4], bf1[4];
                lds128(bf0, bst + (uint32_t)kc * 1024);
                lds128(bf1, bst + (uint32_t)kc * 1024 + 512);
#pragma unroll
                for (int mb = 0; mb < 2; mb++) {
                    uint32_t a[4];
                    ldmatrix_x4(a[0], a[1], a[2], a[3],
                                abuf + (uint32_t)mb * 1280 + kc * 32);
                    mma16816(C[mb][0], a, bf0[0], bf0[1]);
                    mma16816(C[mb][1], a, bf0[2], bf0[3]);
                    mma16816(C[mb][2], a, bf1[0], bf1[1]);
                    mma16816(C[mb][3], a, bf1[2], bf1[3]);
                }
            }
            if (++cons_buf == NBUF_) cons_buf = 0;
        }

        // ---- epilogue: bias + store ----
        {
            int oo = 2 * (lane & 3);
            float* ob0 = out + ((size_t)b << 20) + nb_node + wid * 32 + (lane >> 2);
#pragma unroll
            for (int mb = 0; mb < 2; mb++) {
                float* ob = ob0 + mb * 16;
#pragma unroll
                for (int nb = 0; nb < 4; nb++) {
                    int o = nb * 8 + oo;
                    float bo0 = bias_s[o], bo1 = bias_s[o + 1];
                    float* p = ob + ((size_t)o << 15);
                    p[0]             = C[mb][nb][0] + bo0;
                    p[1 << 15]       = C[mb][nb][1] + bo1;
                    p[8]             = C[mb][nb][2] + bo0;
                    p[(1 << 15) + 8] = C[mb][nb][3] + bo1;
                }
            }
        }
    }
}

// ============================================================================
extern "C" void kernel_launch(void* const* d_in, const int* in_sizes, int n_in,
                              void* d_out, int out_size) {
    const float* x    = (const float*)d_in[0];
    const float* w    = (const float*)d_in[1];
    const float* bias = (const float*)d_in[2];
    const int*   idx  = (const int*)d_in[3];
    float* out = (float*)d_out;

    (void)cudaFuncSetAttribute(k_main, cudaFuncAttributeMaxDynamicSharedMemorySize,
                               SMEM_TOTAL);

    k_bfrag<<<32, 256>>>(w);
    k_transpose<<<TGRID_, 256>>>(x);
    k_main<<<GRID_, 256, SMEM_TOTAL>>>(bias, idx, out);
}

// round 13
// speedup vs baseline: 1.0473x; 1.0170x over previous
#include <cuda_runtime.h>
#include <cuda_fp16.h>
#include <cstdint>
#include <cstddef>

// ============================================================================
// RandomGraphMixer3D  ==  D[M=BT*N, 32] = gather(A)[M,512] @ W'[512,32] + bias
// R13 = R12 with k_bfrag folded into k_transpose (blocks 0-31 build the
//      B-frag table before transposing; removes a 4.1us serial launch).
//      k_main = exact R9/R12 (measured best; at L1 sector-wavefront floor).
// ============================================================================

#define BT_     16
#define NNODES_ 32768
#define NR_     16
#define NTILES_ 2048          // BT_ * NNODES_/256
#define NBUF_   4
#define PF_     3             // PF_ < NBUF_
#define GRID_   296           // 2 CTAs/SM
#define TGRID_  592           // transpose: 4 blocks/SM
#define TTILES_ 4096          // 128-node transpose tiles

// SMEM layout (bytes) -- k_main
#define OFF_B    0            // 32 KB B-frag table
#define OFF_BIAS 32768        // 128 B
#define OFF_A    32896        // 8 warps x 4 bufs x 2560 B
#define WARP_AB  10240
#define SMEM_TOTAL (32896 + 8*WARP_AB)   // 114816 -> 2 CTAs/SM

__device__ __forceinline__ uint32_t smem_u32(const void* p) {
    uint32_t a;
    asm("{ .reg .u64 t; cvta.to.shared.u64 t, %1; cvt.u32.u64 %0, t; }" : "=r"(a) : "l"(p));
    return a;
}
__device__ __forceinline__ void cp_async16(uint32_t dst, const void* src) {
    asm volatile("cp.async.cg.shared.global [%0], [%1], 16;" :: "r"(dst), "l"(src) : "memory");
}
__device__ __forceinline__ void cp_commit() {
    asm volatile("cp.async.commit_group;" ::: "memory");
}
template <int N> __device__ __forceinline__ void cp_wait() {
    asm volatile("cp.async.wait_group %0;" :: "n"(N) : "memory");
}
__device__ __forceinline__ void ldmatrix_x4(uint32_t& r0, uint32_t& r1,
                                            uint32_t& r2, uint32_t& r3, uint32_t a) {
    asm volatile("ldmatrix.sync.aligned.m8n8.x4.shared.b16 {%0,%1,%2,%3}, [%4];"
                 : "=r"(r0), "=r"(r1), "=r"(r2), "=r"(r3) : "r"(a));
}
__device__ __forceinline__ void lds128(uint32_t* v, uint32_t a) {
    asm volatile("ld.shared.v4.b32 {%0,%1,%2,%3}, [%4];"
                 : "=r"(v[0]), "=r"(v[1]), "=r"(v[2]), "=r"(v[3]) : "r"(a));
}
__device__ __forceinline__ void mma16816(float* c, const uint32_t* a,
                                         uint32_t b0, uint32_t b1) {
    asm volatile(
        "mma.sync.aligned.m16n8k16.row.col.f32.f16.f16.f32 "
        "{%0,%1,%2,%3}, {%4,%5,%6,%7}, {%8,%9}, {%0,%1,%2,%3};"
        : "+f"(c[0]), "+f"(c[1]), "+f"(c[2]), "+f"(c[3])
        : "r"(a[0]), "r"(a[1]), "r"(a[2]), "r"(a[3]), "r"(b0), "r"(b1));
}

// -------- scratch ------------------------------------------------------------
__device__ __align__(128) __half   g_xt[(size_t)BT_ * NNODES_ * 32];  // 32 MB
__device__ __align__(128) uint32_t g_Bfrag[8192];                      // 32 KB

// ============================================================================
// Kernel 1: x[b][c][n] f32 -> xt[b][n][c] f16  +  B-frag table build.
// Persistent, double-buffered transpose (next tile's LDGs in flight across
// the single per-tile sync). Blocks 0-31 additionally compute 256 B-frag
// entries each before their transpose loop (hidden under DRAM latency).
// ============================================================================
__global__ void __launch_bounds__(256)
k_transpose(const float* __restrict__ x, const float* __restrict__ w) {
    __shared__ float tile[2][32][132];
    int tid = threadIdx.x;
    int c = tid >> 3, f0 = tid & 7;          // load mapping
    int node = tid & 127, h = tid >> 7;      // store mapping

    float4 v[4];
    // initial load (tile t0 = blockIdx.x)
    {
        int t = blockIdx.x;
        int b = t >> 8, n0 = (t & 255) << 7;
        const float4* xb = (const float4*)(x + ((size_t)b << 20)
                                             + ((size_t)c << 15) + n0);
#pragma unroll
        for (int s = 0; s < 4; s++) v[s] = xb[f0 + 8 * s];
    }

    // B-frag table (layout validated R5-R12): blocks 0-31 only.
    if (blockIdx.x < 32) {
        int e = blockIdx.x * 256 + tid;
        int lane = (e >> 2) & 31, j = e & 3;
        int chunk = (e >> 7) & 1, kc = (e >> 8) & 1, r = e >> 9;
        int nb = chunk * 2 + (j >> 1), reg = j & 1;
        int n_o = nb * 8 + (lane >> 2);
        int cc = kc * 16 + 2 * (lane & 3) + reg * 8;
        __half lo = __float2half(w[n_o * 512 + cc * 16 + r]);
        __half hi = __float2half(w[n_o * 512 + (cc + 1) * 16 + r]);
        __half2 hv = __halves2half2(lo, hi);
        g_Bfrag[e] = *(uint32_t*)&hv;
    }

    int k = 0;
    for (int t = blockIdx.x; t < TTILES_; t += TGRID_, k++) {
        int buf = k & 1;
        // commit current tile's data to smem
#pragma unroll
        for (int s = 0; s < 4; s++)
            *(float4*)&tile[buf][c][4 * (f0 + 8 * s)] = v[s];
        // issue next tile's loads (in flight across sync + read phase)
        int nx = t + TGRID_;
        if (nx < TTILES_) {
            int b = nx >> 8, n0 = (nx & 255) << 7;
            const float4* xb = (const float4*)(x + ((size_t)b << 20)
                                                 + ((size_t)c << 15) + n0);
#pragma unroll
            for (int s = 0; s < 4; s++) v[s] = xb[f0 + 8 * s];
        }
        __syncthreads();
        // read + convert + store tile t
        {
            int b = t >> 8, n0 = (t & 255) << 7;
            float f[16];
#pragma unroll
            for (int j = 0; j < 16; j++) f[j] = tile[buf][16 * h + j][node];
            uint32_t u[8];
#pragma unroll
            for (int j = 0; j < 8; j++) {
                __half2 hh = __floats2half2_rn(f[2 * j], f[2 * j + 1]);
                u[j] = *(uint32_t*)&hh;
            }
            char* dst = (char*)g_xt + ((size_t)b << 21)
                      + (size_t)(n0 + node) * 64 + h * 32;
            *(uint4*)dst        = make_uint4(u[0], u[1], u[2], u[3]);
            *(uint4*)(dst + 16) = make_uint4(u[4], u[5], u[6], u[7]);
        }
        // buffer reuse (write at k+2) is fenced by the sync at k+1
    }
}

// ============================================================================
// Kernel 2: persistent gather-GEMM (exact R9/R12; 296 CTAs x 256, 2/SM)
// ============================================================================
__global__ void __launch_bounds__(256, 2)
k_main(const float* __restrict__ bias, const int* __restrict__ idxg,
       float* __restrict__ out) {
    extern __shared__ char smem[];
    uint32_t sb = smem_u32(smem);
    int tid = threadIdx.x;
    int wid = tid >> 5, lane = tid & 31;

    int nt = 0;
    for (int t = blockIdx.x; t < NTILES_; t += GRID_) nt++;

    const float* bias_s = (const float*)(smem + OFF_BIAS);
    uint32_t aw_base = sb + OFF_A + (uint32_t)wid * WARP_AB;

    uint32_t curi[8], nxti[8];
    auto idx_fetch = [&](int ti, uint32_t* dst) {
        int nbase = (ti & 127) << 8;
        const int4* src = (const int4*)idxg
                        + ((size_t)(nbase + wid * 32 + lane) << 2);
#pragma unroll
        for (int q = 0; q < 4; q++) {
            int4 v = __ldg(src + q);
            dst[2 * q]     = ((uint32_t)v.x & 0xFFFFu) | ((uint32_t)v.y << 16);
            dst[2 * q + 1] = ((uint32_t)v.z & 0xFFFFu) | ((uint32_t)v.w << 16);
        }
    };

    auto gather = [&](int ip, int r, int buf, const uint32_t* idxp) {
        int t = blockIdx.x + ip * GRID_;
        int b = t >> 7;
        const char* xtb = (const char*)g_xt + ((size_t)b << 21);
        uint32_t abase = aw_base + (uint32_t)buf * 2560;
        int u = lane & 3;
#pragma unroll
        for (int p = 0; p < 4; p++) {
            int row = (lane >> 2) + p * 8;
            uint32_t pk = __shfl_sync(0xffffffffu, idxp[r >> 1], row);
            uint32_t g = (r & 1) ? (pk >> 16) : (pk & 0xFFFFu);
            cp_async16(abase + (uint32_t)row * 80 + (uint32_t)u * 16,
                       xtb + ((size_t)g << 6) + u * 16);
        }
    };

    // ---- prologue: B table + bias; idx(tile0); PF gathers ----
    {
        const char* src = (const char*)g_Bfrag;
#pragma unroll
        for (int k = 0; k < 8; k++)
            cp_async16(sb + OFF_B + (uint32_t)(tid + k * 256) * 16,
                       src + (tid + k * 256) * 16);
        if (tid < 8)
            cp_async16(sb + OFF_BIAS + (uint32_t)tid * 16,
                       (const char*)bias + tid * 16);
        cp_commit();
        cp_wait<0>();
        __syncthreads();     // only barrier (B-table visibility)
    }
    if (nt == 0) return;
    idx_fetch(blockIdx.x, curi);
#pragma unroll
    for (int s = 0; s < PF_; s++) { gather(0, s, s, curi); cp_commit(); }

    uint32_t a_lane_off = (uint32_t)(lane & 15) * 80 + ((lane >> 4) << 4);
    uint32_t b_lane = sb + OFF_B + (uint32_t)lane * 16;

    int cons_buf = 0, pf_buf = PF_;

    for (int i = 0; i < nt; i++) {
        int t = blockIdx.x + i * GRID_;
        int b = t >> 7;
        int nb_node = (t & 127) << 8;

        float C[2][4][4];
#pragma unroll
        for (int mb = 0; mb < 2; mb++)
#pragma unroll
            for (int nb = 0; nb < 4; nb++)
#pragma unroll
                for (int j = 0; j < 4; j++) C[mb][nb][j] = 0.0f;

#pragma unroll
        for (int r = 0; r < NR_; r++) {
            if (r == 0) {
                int tsafe = (i + 1 < nt) ? (blockIdx.x + (i + 1) * GRID_)
                                         : blockIdx.x;
                idx_fetch(tsafe, nxti);
            }
            if (r == 13) {     // PF=3: gathers cross tile boundary at r>=13
#pragma unroll
                for (int q = 0; q < 8; q++) curi[q] = nxti[q];
            }
            {
                int ip  = i + ((r + PF_) >> 4);
                int pfr = (r + PF_) & 15;
                if (ip < nt) gather(ip, pfr, pf_buf, curi);
                cp_commit();
                if (++pf_buf == NBUF_) pf_buf = 0;
            }
            cp_wait<PF_>();

            uint32_t abuf = aw_base + (uint32_t)cons_buf * 2560 + a_lane_off;
            uint32_t bst = b_lane + (uint32_t)r * 2048;
#pragma unroll
            for (int kc = 0; kc < 2; kc++) {
                uint32_t bf0[4], bf1[4];
                lds128(bf0, bst + (uint32_t)kc * 1024);
                lds128(bf1, bst + (uint32_t)kc * 1024 + 512);
#pragma unroll
                for (int mb = 0; mb < 2; mb++) {
                    uint32_t a[4];
                    ldmatrix_x4(a[0], a[1], a[2], a[3],
                                abuf + (uint32_t)mb * 1280 + kc * 32);
                    mma16816(C[mb][0], a, bf0[0], bf0[1]);
                    mma16816(C[mb][1], a, bf0[2], bf0[3]);
                    mma16816(C[mb][2], a, bf1[0], bf1[1]);
                    mma16816(C[mb][3], a, bf1[2], bf1[3]);
                }
            }
            if (++cons_buf == NBUF_) cons_buf = 0;
        }

        // ---- epilogue: bias + store ----
        {
            int oo = 2 * (lane & 3);
            float* ob0 = out + ((size_t)b << 20) + nb_node + wid * 32 + (lane >> 2);
#pragma unroll
            for (int mb = 0; mb < 2; mb++) {
                float* ob = ob0 + mb * 16;
#pragma unroll
                for (int nb = 0; nb < 4; nb++) {
                    int o = nb * 8 + oo;
                    float bo0 = bias_s[o], bo1 = bias_s[o + 1];
                    float* p = ob + ((size_t)o << 15);
                    p[0]             = C[mb][nb][0] + bo0;
                    p[1 << 15]       = C[mb][nb][1] + bo1;
                    p[8]             = C[mb][nb][2] + bo0;
                    p[(1 << 15) + 8] = C[mb][nb][3] + bo1;
                }
            }
        }
    }
}

// ============================================================================
extern "C" void kernel_launch(void* const* d_in, const int* in_sizes, int n_in,
                              void* d_out, int out_size) {
    const float* x    = (const float*)d_in[0];
    const float* w    = (const float*)d_in[1];
    const float* bias = (const float*)d_in[2];
    const int*   idx  = (const int*)d_in[3];
    float* out = (float*)d_out;

    (void)cudaFuncSetAttribute(k_main, cudaFuncAttributeMaxDynamicSharedMemorySize,
                               SMEM_TOTAL);

    k_transpose<<<TGRID_, 256>>>(x, w);
    k_main<<<GRID_, 256, SMEM_TOTAL>>>(bias, idx, out);
}